// round 12
// baseline (speedup 1.0000x reference)
#include <cuda_runtime.h>
#include <cuda_bf16.h>
#include <cstdint>
#include <cstddef>

#define BATCH 512
#define NIN   2048
#define UNITS 4096
#define KTOT  6144
#define OFS   (BATCH*UNITS)

#define BM 128
#define BN 128
#define BK 128
#define STAGES 3
#define NKS (KTOT/BK)          // 48
#define TILE_BYTES 32768u      // 128 rows x 256 B
#define STAGE_BYTES 65536u
#define GEMM_SMEM (STAGES*STAGE_BYTES + 1024u)   // 197632

#define SWZB(x) ((x) ^ (((x) >> 4) & 0x70u))     // 256-B pitch swizzle

#define NPKB (BATCH*KTOT/512)      // 6144
#define NDGB (UNITS/256)           // 16
#define FLAG_TARGET 128u

#define C_EL      (-70.6f)
#define C_THR     (-50.4f)
#define C_DTGLC   ((float)(30.0/281.0))
#define C_INVCAP  ((float)(1.0/281.0))
#define C_DTTAUW  ((float)(1.0/144.0))
#define C_DTATAUW ((float)(4.0/144.0))
#define C_BW      (0.0805f)
#define C_VRST    (-70.6f)
#define C_CLIP    (281.0f)

__device__ __nv_bfloat16 g_Apack[(size_t)BATCH * KTOT];
__device__ __nv_bfloat16 g_Wbf[(size_t)KTOT * UNITS];
__device__ float g_diag[UNITS];
__device__ unsigned int g_flag[NKS];

__device__ __forceinline__ uint32_t smem_u32(const void* p) {
    uint32_t a;
    asm("{ .reg .u64 t; cvta.to.shared.u64 t, %1; cvt.u32.u64 %0, t; }"
        : "=r"(a) : "l"(p));
    return a;
}
__device__ __forceinline__ void cp16(uint32_t saddr, const void* g) {
    asm volatile("cp.async.cg.shared.global [%0], [%1], 16;"
                 :: "r"(saddr), "l"(g));
}
__device__ __forceinline__ void ldmx4(uint32_t& r0, uint32_t& r1,
                                      uint32_t& r2, uint32_t& r3, uint32_t a) {
    asm volatile("ldmatrix.sync.aligned.m8n8.x4.shared.b16 {%0,%1,%2,%3}, [%4];"
                 : "=r"(r0), "=r"(r1), "=r"(r2), "=r"(r3) : "r"(a));
}
__device__ __forceinline__ void ldmx4t(uint32_t& r0, uint32_t& r1,
                                       uint32_t& r2, uint32_t& r3, uint32_t a) {
    asm volatile("ldmatrix.sync.aligned.m8n8.x4.trans.shared.b16 {%0,%1,%2,%3}, [%4];"
                 : "=r"(r0), "=r"(r1), "=r"(r2), "=r"(r3) : "r"(a));
}
__device__ __forceinline__ void mma16816(float& d0, float& d1, float& d2, float& d3,
                                         uint32_t a0, uint32_t a1, uint32_t a2, uint32_t a3,
                                         uint32_t b0, uint32_t b1) {
    asm volatile(
        "mma.sync.aligned.m16n8k16.row.col.f32.bf16.bf16.f32 "
        "{%0,%1,%2,%3}, {%4,%5,%6,%7}, {%8,%9}, {%0,%1,%2,%3};"
        : "+f"(d0), "+f"(d1), "+f"(d2), "+f"(d3)
        : "r"(a0), "r"(a1), "r"(a2), "r"(a3), "r"(b0), "r"(b1));
}
__device__ __forceinline__ void wait_flag(int s) {
    uint32_t f;
    do {
        asm volatile("ld.acquire.gpu.u32 %0, [%1];"
                     : "=r"(f) : "l"(g_flag + s) : "memory");
    } while (f < FLAG_TARGET);
}
__device__ __forceinline__ void flag_add(int s) {
    asm volatile("red.release.gpu.add.u32 [%0], 1;"
                 :: "l"(g_flag + s) : "memory");
}

// convert one W row (fp32 -> bf16): slice kc, row = kc*BK + cta
__device__ __forceinline__ void convert_shard(int kc, int cta, int tid,
                                              const float* __restrict__ Win,
                                              const float* __restrict__ Wrec) {
    int k = kc * BK + cta;
    const float* src = (k < NIN) ? (Win + (size_t)k * UNITS)
                                 : (Wrec + (size_t)(k - NIN) * UNITS);
    __nv_bfloat16* dst = g_Wbf + (size_t)k * UNITS;
    #pragma unroll
    for (int i = 0; i < 4; i++) {
        int idx = tid + i * 256;    // float4 index 0..1023
        float4 f = reinterpret_cast<const float4*>(src)[idx];
        __nv_bfloat162 p0 = __floats2bfloat162_rn(f.x, f.y);
        __nv_bfloat162 p1 = __floats2bfloat162_rn(f.z, f.w);
        uint2 pk;
        pk.x = *reinterpret_cast<uint32_t*>(&p0);
        pk.y = *reinterpret_cast<uint32_t*>(&p1);
        reinterpret_cast<uint2*>(dst)[idx] = pk;
    }
}

// ---------------- prep: pack A, extract diag, zero flags ----------------
__global__ void __launch_bounds__(256)
prep_kernel(const float* __restrict__ inp, const float* __restrict__ z,
            const float* __restrict__ Wrec) {
    int blk = blockIdx.x;
    int tid = threadIdx.x;
    if (blk < NPKB) {
        int idx = blk * 256 + tid;
        int b = idx / (KTOT / 2);
        int c = idx - b * (KTOT / 2);
        int k = 2 * c;
        float x0, x1;
        if (k < NIN) {
            const float* p = inp + (size_t)b * NIN + k;
            x0 = p[0]; x1 = p[1];
        } else {
            const float* p = z + (size_t)b * UNITS + (k - NIN);
            x0 = p[0]; x1 = p[1];
        }
        reinterpret_cast<__nv_bfloat162*>(g_Apack)[idx] = __floats2bfloat162_rn(x0, x1);
    } else if (blk < NPKB + NDGB) {
        int n = (blk - NPKB) * 256 + tid;
        g_diag[n] = __bfloat162float(__float2bfloat16(Wrec[(size_t)n * UNITS + n]));
    } else {
        if (tid < NKS) g_flag[tid] = 0u;
    }
}

// ---------------- stage loader (256 threads; identical to R5) -----------
__device__ __forceinline__ void load_stage(uint32_t tiles, int tid,
                                           const __nv_bfloat16* Ag,
                                           const __nv_bfloat16* Bg,
                                           int ks, int s) {
    uint32_t abase = tiles + (uint32_t)s * STAGE_BYTES;
    uint32_t bbase = abase + TILE_BYTES;
    const __nv_bfloat16* ag = Ag + ks * BK;
    const __nv_bfloat16* bg = Bg + (size_t)(ks * BK) * UNITS;
    #pragma unroll
    for (int i = 0; i < 8; i++) {
        int id = tid + i * 256;
        int row = id >> 4, cg = id & 15;
        uint32_t off = SWZB((uint32_t)(row * 256 + cg * 16));
        cp16(abase + off, ag + (size_t)row * KTOT + cg * 8);
    }
    #pragma unroll
    for (int i = 0; i < 8; i++) {
        int id = tid + i * 256;
        int row = id >> 4, cg = id & 15;
        uint32_t off = SWZB((uint32_t)(row * 256 + cg * 16));
        cp16(bbase + off, bg + (size_t)row * UNITS + cg * 8);
    }
}

// ---------------- AdEx elementwise ----------------
__device__ __forceinline__ void adex_one(float it, float vo, float wo, float zo,
                                         int ro, float& nv, float& nz,
                                         float& nw, float& nr) {
    float ex = expf((vo - C_THR) * 0.5f);
    ex = fminf(ex, C_CLIP);
    float nv0 = vo - C_DTGLC * (vo - C_EL) + (2.0f * C_DTGLC) * ex
              + (it - wo) * C_INVCAP;
    nv = (zo > 0.5f) ? C_VRST : nv0;
    nw = wo - wo * C_DTTAUW + C_DTATAUW * (vo - C_EL) + C_BW * zo;
    bool sp = (nv > C_THR) && (ro <= 0);
    nz = sp ? 1.0f : 0.0f;
    int nri = ro - 1 + (sp ? 2 : 0);
    nri = nri < 0 ? 0 : (nri > 2 ? 2 : nri);
    nr = (float)nri;
}

// ---------------- GEMM (R5 core) + in-grid W-convert + AdEx epilogue ----
__global__ void __launch_bounds__(256, 1)
adex_gemm_kernel(const float* __restrict__ v_in, const int* __restrict__ r_in,
                 const float* __restrict__ w_in, const float* __restrict__ z_in,
                 const float* __restrict__ Win, const float* __restrict__ Wrec,
                 float* __restrict__ out) {
    extern __shared__ char smem[];
    uint32_t tiles = (smem_u32(smem) + 1023u) & ~1023u;
    int tid = threadIdx.x;
    int wid = tid >> 5;
    int lane = tid & 31;
    int bid = blockIdx.x;

    int m0 = (bid & 3) * BM;
    int n0 = (bid >> 2) * BN;
    int wm = (wid & 1) * 64;
    int wn = (wid >> 1) * 32;

    const __nv_bfloat16* Ag = g_Apack + (size_t)m0 * KTOT;
    const __nv_bfloat16* Bg = g_Wbf + n0;

    float acc[4][4][4];
    #pragma unroll
    for (int i = 0; i < 4; i++)
        #pragma unroll
        for (int j = 0; j < 4; j++)
            #pragma unroll
            for (int q = 0; q < 4; q++) acc[i][j][q] = 0.0f;

    // ---- prologue: convert slices 0..4 (this CTA's row of each) ----
    #pragma unroll
    for (int sdx = 0; sdx < 5; ++sdx)
        convert_shard(sdx, bid, tid, Win, Wrec);
    __threadfence();
    __syncthreads();
    if (tid == 0)
        for (int sdx = 0; sdx < 5; ++sdx) flag_add(sdx);

    wait_flag(0);
    load_stage(tiles, tid, Ag, Bg, 0, 0);
    asm volatile("cp.async.commit_group;");
    wait_flag(1);
    load_stage(tiles, tid, Ag, Bg, 1, 1);
    asm volatile("cp.async.commit_group;");

    int lrow = lane & 15;
    int lcg  = (lane >> 4) * 16;

    uint32_t aoff[4];
    #pragma unroll
    for (int mf = 0; mf < 4; ++mf)
        aoff[mf] = (uint32_t)((wm + mf * 16 + lrow) * 256 + lcg);
    uint32_t boff[2];
    #pragma unroll
    for (int p = 0; p < 2; ++p)
        boff[p] = (uint32_t)(lrow * 256 + wn * 2 + p * 32 + lcg);

    int s = 0, sn = STAGES - 1;
    for (int ks = 0; ks < NKS; ++ks) {
        asm volatile("cp.async.wait_group %0;" :: "n"(1));
        __syncthreads();

        // publish flag for slice converted last iteration (ks-1 → slice ks+4)
        if (tid == 0 && ks >= 1 && ks + 4 < NKS) flag_add(ks + 4);

        int kn = ks + 2;
        if (kn < NKS) {
            wait_flag(kn);
            load_stage(tiles, tid, Ag, Bg, kn, sn);
        }
        asm volatile("cp.async.commit_group;");

        // convert this CTA's row of slice ks+5 (latency hidden by compute)
        bool conv = (ks + 5 < NKS);
        if (conv) convert_shard(ks + 5, bid, tid, Win, Wrec);

        uint32_t abase = tiles + (uint32_t)s * STAGE_BYTES;
        uint32_t bbase = abase + TILE_BYTES;

        uint32_t af[2][4][4], bfr[2][4][2];

        #pragma unroll
        for (int mf = 0; mf < 4; ++mf)
            ldmx4(af[0][mf][0], af[0][mf][1], af[0][mf][2], af[0][mf][3],
                  abase + SWZB(aoff[mf]));
        #pragma unroll
        for (int p = 0; p < 2; ++p) {
            uint32_t r0, r1, r2, r3;
            ldmx4t(r0, r1, r2, r3, bbase + SWZB(boff[p]));
            bfr[0][p * 2 + 0][0] = r0; bfr[0][p * 2 + 0][1] = r1;
            bfr[0][p * 2 + 1][0] = r2; bfr[0][p * 2 + 1][1] = r3;
        }

        #pragma unroll
        for (int kk = 0; kk < BK / 16; ++kk) {
            int cur = kk & 1, nxt = cur ^ 1;
            if (kk < BK / 16 - 1) {
                uint32_t kba = (uint32_t)((kk + 1) * 32);
                uint32_t kbb = (uint32_t)((kk + 1) * 4096);
                #pragma unroll
                for (int mf = 0; mf < 4; ++mf)
                    ldmx4(af[nxt][mf][0], af[nxt][mf][1],
                          af[nxt][mf][2], af[nxt][mf][3],
                          abase + SWZB(aoff[mf] + kba));
                #pragma unroll
                for (int p = 0; p < 2; ++p) {
                    uint32_t r0, r1, r2, r3;
                    ldmx4t(r0, r1, r2, r3, bbase + SWZB(boff[p] + kbb));
                    bfr[nxt][p * 2 + 0][0] = r0; bfr[nxt][p * 2 + 0][1] = r1;
                    bfr[nxt][p * 2 + 1][0] = r2; bfr[nxt][p * 2 + 1][1] = r3;
                }
            }
            #pragma unroll
            for (int mf = 0; mf < 4; ++mf)
                #pragma unroll
                for (int nf = 0; nf < 4; ++nf)
                    mma16816(acc[mf][nf][0], acc[mf][nf][1],
                             acc[mf][nf][2], acc[mf][nf][3],
                             af[cur][mf][0], af[cur][mf][1],
                             af[cur][mf][2], af[cur][mf][3],
                             bfr[cur][nf][0], bfr[cur][nf][1]);
        }

        // make this iteration's converted STGs globally visible before the
        // flag_add that happens after next iteration's barrier
        if (conv) __threadfence();

        s = (s + 1 == STAGES) ? 0 : s + 1;
        sn = (sn + 1 == STAGES) ? 0 : sn + 1;
    }

    // ------------- epilogue (identical to R5) -------------
    int gid = lane >> 2;
    int qn  = (lane & 3) * 2;

    #pragma unroll
    for (int mf = 0; mf < 4; ++mf) {
        #pragma unroll
        for (int g = 0; g < 2; ++g) {
            int b = m0 + wm + mf * 16 + g * 8 + gid;
            size_t rowbase = (size_t)b * UNITS + n0 + wn;
            #pragma unroll
            for (int nf = 0; nf < 4; ++nf) {
                size_t ofs = rowbase + nf * 8 + qn;
                int ncol = n0 + wn + nf * 8 + qn;
                float2 vv = *reinterpret_cast<const float2*>(v_in + ofs);
                float2 ww = *reinterpret_cast<const float2*>(w_in + ofs);
                float2 zz = *reinterpret_cast<const float2*>(z_in + ofs);
                int2   rr = *reinterpret_cast<const int2*>(r_in + ofs);
                float2 dg = *reinterpret_cast<const float2*>(g_diag + ncol);
                float i0 = acc[mf][nf][g * 2 + 0] - zz.x * dg.x;
                float i1 = acc[mf][nf][g * 2 + 1] - zz.y * dg.y;
                float2 ov, oz, ow, orr;
                adex_one(i0, vv.x, ww.x, zz.x, rr.x, ov.x, oz.x, ow.x, orr.x);
                adex_one(i1, vv.y, ww.y, zz.y, rr.y, ov.y, oz.y, ow.y, orr.y);
                *reinterpret_cast<float2*>(out + 0 * (size_t)OFS + ofs) = ov;
                *reinterpret_cast<float2*>(out + 1 * (size_t)OFS + ofs) = oz;
                *reinterpret_cast<float2*>(out + 2 * (size_t)OFS + ofs) = ow;
                *reinterpret_cast<float2*>(out + 3 * (size_t)OFS + ofs) = orr;
            }
        }
    }
}

// ---------------- launch ----------------
extern "C" void kernel_launch(void* const* d_in, const int* in_sizes, int n_in,
                              void* d_out, int out_size) {
    const float* inputs = (const float*)d_in[0];
    const float* v      = (const float*)d_in[1];
    const int*   r      = (const int*)d_in[2];
    const float* w      = (const float*)d_in[3];
    const float* z      = (const float*)d_in[4];
    const float* Win    = (const float*)d_in[5];
    const float* Wrec   = (const float*)d_in[6];
    float* out = (float*)d_out;
    (void)in_sizes; (void)n_in; (void)out_size;

    cudaFuncSetAttribute(adex_gemm_kernel,
                         cudaFuncAttributeMaxDynamicSharedMemorySize, GEMM_SMEM);

    prep_kernel<<<NPKB + NDGB + 1, 256>>>(inputs, z, Wrec);
    adex_gemm_kernel<<<128, 256, GEMM_SMEM>>>(v, r, w, z, Win, Wrec, out);
}

// round 13
// speedup vs baseline: 1.3974x; 1.3974x over previous
#include <cuda_runtime.h>
#include <cuda_bf16.h>
#include <cstdint>
#include <cstddef>

#define BATCH 512
#define NIN   2048
#define UNITS 4096
#define KTOT  6144
#define OFS   (BATCH*UNITS)

#define BM 128
#define BN 128
#define BK 128
#define STAGES 3
#define NKS (KTOT/BK)          // 48
#define TILE_BYTES 32768u      // 128 rows x 256 B
#define STAGE_BYTES 65536u
#define GEMM_SMEM (STAGES*STAGE_BYTES + 1024u)   // 197632

#define SWZB(x) ((x) ^ (((x) >> 4) & 0x70u))     // 256-B pitch swizzle

#define NWCB ((KTOT*UNITS/4)/256)  // 24576
#define NPKB (BATCH*KTOT/512)      // 6144
#define NDGB (UNITS/256)           // 16

#define C_EL      (-70.6f)
#define C_THR     (-50.4f)
#define C_DTGLC   ((float)(30.0/281.0))
#define C_INVCAP  ((float)(1.0/281.0))
#define C_DTTAUW  ((float)(1.0/144.0))
#define C_DTATAUW ((float)(4.0/144.0))
#define C_BW      (0.0805f)
#define C_VRST    (-70.6f)
#define C_CLIP    (281.0f)

__device__ __nv_bfloat16 g_Apack[(size_t)BATCH * KTOT];
__device__ __nv_bfloat16 g_Wbf[(size_t)KTOT * UNITS];
__device__ float g_diag[UNITS];

__device__ __forceinline__ uint32_t smem_u32(const void* p) {
    uint32_t a;
    asm("{ .reg .u64 t; cvta.to.shared.u64 t, %1; cvt.u32.u64 %0, t; }"
        : "=r"(a) : "l"(p));
    return a;
}
__device__ __forceinline__ void cp16(uint32_t saddr, const void* g) {
    asm volatile("cp.async.cg.shared.global [%0], [%1], 16;"
                 :: "r"(saddr), "l"(g));
}
__device__ __forceinline__ void pfL2(const void* g) {
    asm volatile("prefetch.global.L2 [%0];" :: "l"(g));
}
__device__ __forceinline__ void ldmx4(uint32_t& r0, uint32_t& r1,
                                      uint32_t& r2, uint32_t& r3, uint32_t a) {
    asm volatile("ldmatrix.sync.aligned.m8n8.x4.shared.b16 {%0,%1,%2,%3}, [%4];"
                 : "=r"(r0), "=r"(r1), "=r"(r2), "=r"(r3) : "r"(a));
}
__device__ __forceinline__ void ldmx4t(uint32_t& r0, uint32_t& r1,
                                       uint32_t& r2, uint32_t& r3, uint32_t a) {
    asm volatile("ldmatrix.sync.aligned.m8n8.x4.trans.shared.b16 {%0,%1,%2,%3}, [%4];"
                 : "=r"(r0), "=r"(r1), "=r"(r2), "=r"(r3) : "r"(a));
}
__device__ __forceinline__ void mma16816(float& d0, float& d1, float& d2, float& d3,
                                         uint32_t a0, uint32_t a1, uint32_t a2, uint32_t a3,
                                         uint32_t b0, uint32_t b1) {
    asm volatile(
        "mma.sync.aligned.m16n8k16.row.col.f32.bf16.bf16.f32 "
        "{%0,%1,%2,%3}, {%4,%5,%6,%7}, {%8,%9}, {%0,%1,%2,%3};"
        : "+f"(d0), "+f"(d1), "+f"(d2), "+f"(d3)
        : "r"(a0), "r"(a1), "r"(a2), "r"(a3), "r"(b0), "r"(b1));
}

// ---------------- prep: convert W -> bf16, pack A, extract diag ----------
__global__ void __launch_bounds__(256)
prep_kernel(const float* __restrict__ inp, const float* __restrict__ z,
            const float* __restrict__ Win, const float* __restrict__ Wrec) {
    int blk = blockIdx.x;
    int tid = threadIdx.x;
    if (blk < NWCB) {
        size_t e = ((size_t)blk * 256 + tid) * 4;
        const float* src = (e < (size_t)NIN * UNITS)
                         ? (Win + e) : (Wrec + (e - (size_t)NIN * UNITS));
        float4 f = *reinterpret_cast<const float4*>(src);
        __nv_bfloat162 p0 = __floats2bfloat162_rn(f.x, f.y);
        __nv_bfloat162 p1 = __floats2bfloat162_rn(f.z, f.w);
        uint2 pk;
        pk.x = *reinterpret_cast<uint32_t*>(&p0);
        pk.y = *reinterpret_cast<uint32_t*>(&p1);
        reinterpret_cast<uint2*>(g_Wbf)[e / 4] = pk;
    } else if (blk < NWCB + NPKB) {
        int idx = (blk - NWCB) * 256 + tid;
        int b = idx / (KTOT / 2);
        int c = idx - b * (KTOT / 2);
        int k = 2 * c;
        float x0, x1;
        if (k < NIN) {
            const float* p = inp + (size_t)b * NIN + k;
            x0 = p[0]; x1 = p[1];
        } else {
            const float* p = z + (size_t)b * UNITS + (k - NIN);
            x0 = p[0]; x1 = p[1];
        }
        reinterpret_cast<__nv_bfloat162*>(g_Apack)[idx] = __floats2bfloat162_rn(x0, x1);
    } else {
        int n = (blk - NWCB - NPKB) * 256 + tid;
        g_diag[n] = __bfloat162float(__float2bfloat16(Wrec[(size_t)n * UNITS + n]));
    }
}

// ---------------- stage loader ----------------
__device__ __forceinline__ void load_stage(uint32_t tiles, int tid,
                                           const __nv_bfloat16* Ag,
                                           const __nv_bfloat16* Bg,
                                           int ks, int s) {
    uint32_t abase = tiles + (uint32_t)s * STAGE_BYTES;
    uint32_t bbase = abase + TILE_BYTES;
    const __nv_bfloat16* ag = Ag + ks * BK;
    const __nv_bfloat16* bg = Bg + (size_t)(ks * BK) * UNITS;
    #pragma unroll
    for (int i = 0; i < 8; i++) {
        int id = tid + i * 256;
        int row = id >> 4, cg = id & 15;
        uint32_t off = SWZB((uint32_t)(row * 256 + cg * 16));
        cp16(abase + off, ag + (size_t)row * KTOT + cg * 8);
    }
    #pragma unroll
    for (int i = 0; i < 8; i++) {
        int id = tid + i * 256;
        int row = id >> 4, cg = id & 15;
        uint32_t off = SWZB((uint32_t)(row * 256 + cg * 16));
        cp16(bbase + off, bg + (size_t)row * UNITS + cg * 8);
    }
}

// ---------------- AdEx elementwise ----------------
__device__ __forceinline__ void adex_one(float it, float vo, float wo, float zo,
                                         int ro, float& nv, float& nz,
                                         float& nw, float& nr) {
    float ex = expf((vo - C_THR) * 0.5f);
    ex = fminf(ex, C_CLIP);
    float nv0 = vo - C_DTGLC * (vo - C_EL) + (2.0f * C_DTGLC) * ex
              + (it - wo) * C_INVCAP;
    nv = (zo > 0.5f) ? C_VRST : nv0;
    nw = wo - wo * C_DTTAUW + C_DTATAUW * (vo - C_EL) + C_BW * zo;
    bool sp = (nv > C_THR) && (ro <= 0);
    nz = sp ? 1.0f : 0.0f;
    int nri = ro - 1 + (sp ? 2 : 0);
    nri = nri < 0 ? 0 : (nri > 2 ? 2 : nri);
    nr = (float)nri;
}

// ---------------- GEMM (R5 core) + epilogue prefetch + AdEx --------------
__global__ void __launch_bounds__(256, 1)
adex_gemm_kernel(const float* __restrict__ v_in, const int* __restrict__ r_in,
                 const float* __restrict__ w_in, const float* __restrict__ z_in,
                 float* __restrict__ out) {
    extern __shared__ char smem[];
    uint32_t tiles = (smem_u32(smem) + 1023u) & ~1023u;
    int tid = threadIdx.x;
    int wid = tid >> 5;
    int lane = tid & 31;

    int m0 = (blockIdx.x & 3) * BM;
    int n0 = (blockIdx.x >> 2) * BN;
    int wm = (wid & 1) * 64;
    int wn = (wid >> 1) * 32;

    const __nv_bfloat16* Ag = g_Apack + (size_t)m0 * KTOT;
    const __nv_bfloat16* Bg = g_Wbf + n0;

    float acc[4][4][4];
    #pragma unroll
    for (int i = 0; i < 4; i++)
        #pragma unroll
        for (int j = 0; j < 4; j++)
            #pragma unroll
            for (int q = 0; q < 4; q++) acc[i][j][q] = 0.0f;

    #pragma unroll
    for (int s = 0; s < STAGES - 1; ++s) {
        load_stage(tiles, tid, Ag, Bg, s, s);
        asm volatile("cp.async.commit_group;");
    }

    int lrow = lane & 15;
    int lcg  = (lane >> 4) * 16;

    uint32_t aoff[4];
    #pragma unroll
    for (int mf = 0; mf < 4; ++mf)
        aoff[mf] = (uint32_t)((wm + mf * 16 + lrow) * 256 + lcg);
    uint32_t boff[2];
    #pragma unroll
    for (int p = 0; p < 2; ++p)
        boff[p] = (uint32_t)(lrow * 256 + wn * 2 + p * 32 + lcg);

    int gid = lane >> 2;
    int qn  = (lane & 3) * 2;

    int s = 0, sn = STAGES - 1;
    for (int ks = 0; ks < NKS; ++ks) {
        asm volatile("cp.async.wait_group %0;" :: "n"(1));
        __syncthreads();

        int kn = ks + STAGES - 1;
        if (kn < NKS) load_stage(tiles, tid, Ag, Bg, kn, sn);
        asm volatile("cp.async.commit_group;");

        // ---- one-shot epilogue prefetch, ~4 iterations before the end ----
        if (ks == NKS - 4) {
            #pragma unroll
            for (int mf = 0; mf < 4; ++mf) {
                #pragma unroll
                for (int g = 0; g < 2; ++g) {
                    int b = m0 + wm + mf * 16 + g * 8 + gid;
                    size_t ofs = (size_t)b * UNITS + n0 + wn + qn;
                    pfL2(v_in + ofs);
                    pfL2(w_in + ofs);
                    pfL2(z_in + ofs);
                    pfL2(r_in + ofs);
                }
            }
            pfL2(g_diag + n0 + wn + qn);
        }

        uint32_t abase = tiles + (uint32_t)s * STAGE_BYTES;
        uint32_t bbase = abase + TILE_BYTES;

        uint32_t af[2][4][4], bfr[2][4][2];

        #pragma unroll
        for (int mf = 0; mf < 4; ++mf)
            ldmx4(af[0][mf][0], af[0][mf][1], af[0][mf][2], af[0][mf][3],
                  abase + SWZB(aoff[mf]));
        #pragma unroll
        for (int p = 0; p < 2; ++p) {
            uint32_t r0, r1, r2, r3;
            ldmx4t(r0, r1, r2, r3, bbase + SWZB(boff[p]));
            bfr[0][p * 2 + 0][0] = r0; bfr[0][p * 2 + 0][1] = r1;
            bfr[0][p * 2 + 1][0] = r2; bfr[0][p * 2 + 1][1] = r3;
        }

        #pragma unroll
        for (int kk = 0; kk < BK / 16; ++kk) {
            int cur = kk & 1, nxt = cur ^ 1;
            if (kk < BK / 16 - 1) {
                uint32_t kba = (uint32_t)((kk + 1) * 32);
                uint32_t kbb = (uint32_t)((kk + 1) * 4096);
                #pragma unroll
                for (int mf = 0; mf < 4; ++mf)
                    ldmx4(af[nxt][mf][0], af[nxt][mf][1],
                          af[nxt][mf][2], af[nxt][mf][3],
                          abase + SWZB(aoff[mf] + kba));
                #pragma unroll
                for (int p = 0; p < 2; ++p) {
                    uint32_t r0, r1, r2, r3;
                    ldmx4t(r0, r1, r2, r3, bbase + SWZB(boff[p] + kbb));
                    bfr[nxt][p * 2 + 0][0] = r0; bfr[nxt][p * 2 + 0][1] = r1;
                    bfr[nxt][p * 2 + 1][0] = r2; bfr[nxt][p * 2 + 1][1] = r3;
                }
            }
            #pragma unroll
            for (int mf = 0; mf < 4; ++mf)
                #pragma unroll
                for (int nf = 0; nf < 4; ++nf)
                    mma16816(acc[mf][nf][0], acc[mf][nf][1],
                             acc[mf][nf][2], acc[mf][nf][3],
                             af[cur][mf][0], af[cur][mf][1],
                             af[cur][mf][2], af[cur][mf][3],
                             bfr[cur][nf][0], bfr[cur][nf][1]);
        }

        s = (s + 1 == STAGES) ? 0 : s + 1;
        sn = (sn + 1 == STAGES) ? 0 : sn + 1;
    }

    // ------------- epilogue -------------
    #pragma unroll
    for (int mf = 0; mf < 4; ++mf) {
        #pragma unroll
        for (int g = 0; g < 2; ++g) {
            int b = m0 + wm + mf * 16 + g * 8 + gid;
            size_t rowbase = (size_t)b * UNITS + n0 + wn;
            #pragma unroll
            for (int nf = 0; nf < 4; ++nf) {
                size_t ofs = rowbase + nf * 8 + qn;
                int ncol = n0 + wn + nf * 8 + qn;
                float2 vv = *reinterpret_cast<const float2*>(v_in + ofs);
                float2 ww = *reinterpret_cast<const float2*>(w_in + ofs);
                float2 zz = *reinterpret_cast<const float2*>(z_in + ofs);
                int2   rr = *reinterpret_cast<const int2*>(r_in + ofs);
                float2 dg = *reinterpret_cast<const float2*>(g_diag + ncol);
                float i0 = acc[mf][nf][g * 2 + 0] - zz.x * dg.x;
                float i1 = acc[mf][nf][g * 2 + 1] - zz.y * dg.y;
                float2 ov, oz, ow, orr;
                adex_one(i0, vv.x, ww.x, zz.x, rr.x, ov.x, oz.x, ow.x, orr.x);
                adex_one(i1, vv.y, ww.y, zz.y, rr.y, ov.y, oz.y, ow.y, orr.y);
                *reinterpret_cast<float2*>(out + 0 * (size_t)OFS + ofs) = ov;
                *reinterpret_cast<float2*>(out + 1 * (size_t)OFS + ofs) = oz;
                *reinterpret_cast<float2*>(out + 2 * (size_t)OFS + ofs) = ow;
                *reinterpret_cast<float2*>(out + 3 * (size_t)OFS + ofs) = orr;
            }
        }
    }
}

// ---------------- launch ----------------
extern "C" void kernel_launch(void* const* d_in, const int* in_sizes, int n_in,
                              void* d_out, int out_size) {
    const float* inputs = (const float*)d_in[0];
    const float* v      = (const float*)d_in[1];
    const int*   r      = (const int*)d_in[2];
    const float* w      = (const float*)d_in[3];
    const float* z      = (const float*)d_in[4];
    const float* Win    = (const float*)d_in[5];
    const float* Wrec   = (const float*)d_in[6];
    float* out = (float*)d_out;
    (void)in_sizes; (void)n_in; (void)out_size;

    cudaFuncSetAttribute(adex_gemm_kernel,
                         cudaFuncAttributeMaxDynamicSharedMemorySize, GEMM_SMEM);

    prep_kernel<<<NWCB + NPKB + NDGB, 256>>>(inputs, z, Win, Wrec);
    adex_gemm_kernel<<<128, 256, GEMM_SMEM>>>(v, r, w, z, out);
}

// round 14
// speedup vs baseline: 1.4730x; 1.0541x over previous
#include <cuda_runtime.h>
#include <cuda_bf16.h>
#include <cstdint>
#include <cstddef>

#define BATCH 512
#define NIN   2048
#define UNITS 4096
#define KTOT  6144
#define OFS   (BATCH*UNITS)

#define BM 128
#define BN 64
#define BK 64                  // K per stage
#define STAGES 4
#define NKS (KTOT/BK)          // 96
#define A_BYTES 16384u         // 128 m-rows x 128 B
#define B_BYTES 8192u          // 64 k-rows x 128 B
#define STAGE_BYTES 24576u
#define GEMM_SMEM (STAGES*STAGE_BYTES + 1024u)   // 99328 -> 2 CTAs/SM

#define SWZA(x) ((x) ^ (((x) >> 3) & 0x70u))     // 128-B pitch swizzle

#define NWCB ((KTOT*UNITS/4)/256)  // 24576
#define NPKB (BATCH*KTOT/512)      // 6144
#define NDGB (UNITS/256)           // 16

#define C_EL      (-70.6f)
#define C_THR     (-50.4f)
#define C_DTGLC   ((float)(30.0/281.0))
#define C_INVCAP  ((float)(1.0/281.0))
#define C_DTTAUW  ((float)(1.0/144.0))
#define C_DTATAUW ((float)(4.0/144.0))
#define C_BW      (0.0805f)
#define C_VRST    (-70.6f)
#define C_CLIP    (281.0f)

__device__ __nv_bfloat16 g_Apack[(size_t)BATCH * KTOT];
__device__ __nv_bfloat16 g_Wbf[(size_t)KTOT * UNITS];
__device__ float g_diag[UNITS];

__device__ __forceinline__ uint32_t smem_u32(const void* p) {
    uint32_t a;
    asm("{ .reg .u64 t; cvta.to.shared.u64 t, %1; cvt.u32.u64 %0, t; }"
        : "=r"(a) : "l"(p));
    return a;
}
__device__ __forceinline__ void cp16(uint32_t saddr, const void* g) {
    asm volatile("cp.async.cg.shared.global [%0], [%1], 16;"
                 :: "r"(saddr), "l"(g));
}
__device__ __forceinline__ void ldmx4(uint32_t& r0, uint32_t& r1,
                                      uint32_t& r2, uint32_t& r3, uint32_t a) {
    asm volatile("ldmatrix.sync.aligned.m8n8.x4.shared.b16 {%0,%1,%2,%3}, [%4];"
                 : "=r"(r0), "=r"(r1), "=r"(r2), "=r"(r3) : "r"(a));
}
__device__ __forceinline__ void ldmx4t(uint32_t& r0, uint32_t& r1,
                                       uint32_t& r2, uint32_t& r3, uint32_t a) {
    asm volatile("ldmatrix.sync.aligned.m8n8.x4.trans.shared.b16 {%0,%1,%2,%3}, [%4];"
                 : "=r"(r0), "=r"(r1), "=r"(r2), "=r"(r3) : "r"(a));
}
__device__ __forceinline__ void mma16816(float& d0, float& d1, float& d2, float& d3,
                                         uint32_t a0, uint32_t a1, uint32_t a2, uint32_t a3,
                                         uint32_t b0, uint32_t b1) {
    asm volatile(
        "mma.sync.aligned.m16n8k16.row.col.f32.bf16.bf16.f32 "
        "{%0,%1,%2,%3}, {%4,%5,%6,%7}, {%8,%9}, {%0,%1,%2,%3};"
        : "+f"(d0), "+f"(d1), "+f"(d2), "+f"(d3)
        : "r"(a0), "r"(a1), "r"(a2), "r"(a3), "r"(b0), "r"(b1));
}

// ---------------- prep: convert W -> bf16, pack A, extract diag ----------
__global__ void __launch_bounds__(256)
prep_kernel(const float* __restrict__ inp, const float* __restrict__ z,
            const float* __restrict__ Win, const float* __restrict__ Wrec) {
    int blk = blockIdx.x;
    int tid = threadIdx.x;
    if (blk < NWCB) {
        size_t e = ((size_t)blk * 256 + tid) * 4;
        const float* src = (e < (size_t)NIN * UNITS)
                         ? (Win + e) : (Wrec + (e - (size_t)NIN * UNITS));
        float4 f = *reinterpret_cast<const float4*>(src);
        __nv_bfloat162 p0 = __floats2bfloat162_rn(f.x, f.y);
        __nv_bfloat162 p1 = __floats2bfloat162_rn(f.z, f.w);
        uint2 pk;
        pk.x = *reinterpret_cast<uint32_t*>(&p0);
        pk.y = *reinterpret_cast<uint32_t*>(&p1);
        reinterpret_cast<uint2*>(g_Wbf)[e / 4] = pk;
    } else if (blk < NWCB + NPKB) {
        int idx = (blk - NWCB) * 256 + tid;
        int b = idx / (KTOT / 2);
        int c = idx - b * (KTOT / 2);
        int k = 2 * c;
        float x0, x1;
        if (k < NIN) {
            const float* p = inp + (size_t)b * NIN + k;
            x0 = p[0]; x1 = p[1];
        } else {
            const float* p = z + (size_t)b * UNITS + (k - NIN);
            x0 = p[0]; x1 = p[1];
        }
        reinterpret_cast<__nv_bfloat162*>(g_Apack)[idx] = __floats2bfloat162_rn(x0, x1);
    } else {
        int n = (blk - NWCB - NPKB) * 256 + tid;
        g_diag[n] = __bfloat162float(__float2bfloat16(Wrec[(size_t)n * UNITS + n]));
    }
}

// ---------------- stage loader (128 threads) ----------------
__device__ __forceinline__ void load_stage(uint32_t tiles, int tid,
                                           const __nv_bfloat16* Ag,
                                           const __nv_bfloat16* Bg,
                                           int ks, int s) {
    uint32_t abase = tiles + (uint32_t)s * STAGE_BYTES;
    uint32_t bbase = abase + A_BYTES;
    const __nv_bfloat16* ag = Ag + ks * BK;
    const __nv_bfloat16* bg = Bg + (size_t)(ks * BK) * UNITS;
    #pragma unroll
    for (int i = 0; i < 8; i++) {           // A: 128 m-rows x 8 chunks(16B)
        int id = tid + i * 128;
        int row = id >> 3, cg = id & 7;
        uint32_t off = SWZA((uint32_t)(row * 128 + cg * 16));
        cp16(abase + off, ag + (size_t)row * KTOT + cg * 8);
    }
    #pragma unroll
    for (int i = 0; i < 4; i++) {           // B: 64 k-rows x 8 chunks(16B)
        int id = tid + i * 128;
        int row = id >> 3, cg = id & 7;
        uint32_t off = SWZA((uint32_t)(row * 128 + cg * 16));
        cp16(bbase + off, bg + (size_t)row * UNITS + cg * 8);
    }
}

// ---------------- AdEx elementwise ----------------
__device__ __forceinline__ void adex_one(float it, float vo, float wo, float zo,
                                         int ro, float& nv, float& nz,
                                         float& nw, float& nr) {
    float ex = expf((vo - C_THR) * 0.5f);
    ex = fminf(ex, C_CLIP);
    float nv0 = vo - C_DTGLC * (vo - C_EL) + (2.0f * C_DTGLC) * ex
              + (it - wo) * C_INVCAP;
    nv = (zo > 0.5f) ? C_VRST : nv0;
    nw = wo - wo * C_DTTAUW + C_DTATAUW * (vo - C_EL) + C_BW * zo;
    bool sp = (nv > C_THR) && (ro <= 0);
    nz = sp ? 1.0f : 0.0f;
    int nri = ro - 1 + (sp ? 2 : 0);
    nri = nri < 0 ? 0 : (nri > 2 ? 2 : nri);
    nr = (float)nri;
}

// ---------------- GEMM: 4 warps, 128x64 CTA tile, 2 CTAs/SM -------------
__global__ void __launch_bounds__(128, 2)
adex_gemm_kernel(const float* __restrict__ v_in, const int* __restrict__ r_in,
                 const float* __restrict__ w_in, const float* __restrict__ z_in,
                 float* __restrict__ out) {
    extern __shared__ char smem[];
    uint32_t tiles = (smem_u32(smem) + 1023u) & ~1023u;
    int tid = threadIdx.x;
    int wid = tid >> 5;
    int lane = tid & 31;

    int m0 = (blockIdx.x & 3) * BM;
    int n0 = (blockIdx.x >> 2) * BN;
    int wm = (wid & 1) * 64;     // 2 warps in M
    int wn = (wid >> 1) * 32;    // 2 warps in N

    const __nv_bfloat16* Ag = g_Apack + (size_t)m0 * KTOT;
    const __nv_bfloat16* Bg = g_Wbf + n0;

    float acc[4][4][4];
    #pragma unroll
    for (int i = 0; i < 4; i++)
        #pragma unroll
        for (int j = 0; j < 4; j++)
            #pragma unroll
            for (int q = 0; q < 4; q++) acc[i][j][q] = 0.0f;

    // prologue: stages 0..2 in flight
    #pragma unroll
    for (int s = 0; s < STAGES - 1; ++s) {
        load_stage(tiles, tid, Ag, Bg, s, s);
        asm volatile("cp.async.commit_group;");
    }

    int lrow = lane & 15;
    int lcg  = (lane >> 4) * 16;

    uint32_t aoff[4];
    #pragma unroll
    for (int mf = 0; mf < 4; ++mf)
        aoff[mf] = (uint32_t)((wm + mf * 16 + lrow) * 128 + lcg);
    uint32_t boff[2];
    #pragma unroll
    for (int p = 0; p < 2; ++p)
        boff[p] = (uint32_t)(lrow * 128 + wn * 2 + p * 32 + lcg);

    for (int ks = 0; ks < NKS; ++ks) {
        int s = ks & (STAGES - 1);
        asm volatile("cp.async.wait_group %0;" :: "n"(2));
        __syncthreads();

        int kn = ks + STAGES - 1;
        if (kn < NKS) load_stage(tiles, tid, Ag, Bg, kn, kn & (STAGES - 1));
        asm volatile("cp.async.commit_group;");

        uint32_t abase = tiles + (uint32_t)s * STAGE_BYTES;
        uint32_t bbase = abase + A_BYTES;

        uint32_t af[2][4][4], bfr[2][4][2];

        #pragma unroll
        for (int mf = 0; mf < 4; ++mf)
            ldmx4(af[0][mf][0], af[0][mf][1], af[0][mf][2], af[0][mf][3],
                  abase + SWZA(aoff[mf]));
        #pragma unroll
        for (int p = 0; p < 2; ++p) {
            uint32_t r0, r1, r2, r3;
            ldmx4t(r0, r1, r2, r3, bbase + SWZA(boff[p]));
            bfr[0][p * 2 + 0][0] = r0; bfr[0][p * 2 + 0][1] = r1;
            bfr[0][p * 2 + 1][0] = r2; bfr[0][p * 2 + 1][1] = r3;
        }

        #pragma unroll
        for (int kk = 0; kk < BK / 16; ++kk) {   // 4 k-steps
            int cur = kk & 1, nxt = cur ^ 1;
            if (kk < BK / 16 - 1) {
                uint32_t kba = (uint32_t)((kk + 1) * 32);    // A: +16 bf16 in k
                uint32_t kbb = (uint32_t)((kk + 1) * 2048);  // B: +16 k-rows
                #pragma unroll
                for (int mf = 0; mf < 4; ++mf)
                    ldmx4(af[nxt][mf][0], af[nxt][mf][1],
                          af[nxt][mf][2], af[nxt][mf][3],
                          abase + SWZA(aoff[mf] + kba));
                #pragma unroll
                for (int p = 0; p < 2; ++p) {
                    uint32_t r0, r1, r2, r3;
                    ldmx4t(r0, r1, r2, r3, bbase + SWZA(boff[p] + kbb));
                    bfr[nxt][p * 2 + 0][0] = r0; bfr[nxt][p * 2 + 0][1] = r1;
                    bfr[nxt][p * 2 + 1][0] = r2; bfr[nxt][p * 2 + 1][1] = r3;
                }
            }
            #pragma unroll
            for (int mf = 0; mf < 4; ++mf)
                #pragma unroll
                for (int nf = 0; nf < 4; ++nf)
                    mma16816(acc[mf][nf][0], acc[mf][nf][1],
                             acc[mf][nf][2], acc[mf][nf][3],
                             af[cur][mf][0], af[cur][mf][1],
                             af[cur][mf][2], af[cur][mf][3],
                             bfr[cur][nf][0], bfr[cur][nf][1]);
        }
    }

    // ------------- epilogue -------------
    int gid = lane >> 2;
    int qn  = (lane & 3) * 2;

    #pragma unroll
    for (int mf = 0; mf < 4; ++mf) {
        #pragma unroll
        for (int g = 0; g < 2; ++g) {
            int b = m0 + wm + mf * 16 + g * 8 + gid;
            size_t rowbase = (size_t)b * UNITS + n0 + wn;
            #pragma unroll
            for (int nf = 0; nf < 4; ++nf) {
                size_t ofs = rowbase + nf * 8 + qn;
                int ncol = n0 + wn + nf * 8 + qn;
                float2 vv = *reinterpret_cast<const float2*>(v_in + ofs);
                float2 ww = *reinterpret_cast<const float2*>(w_in + ofs);
                float2 zz = *reinterpret_cast<const float2*>(z_in + ofs);
                int2   rr = *reinterpret_cast<const int2*>(r_in + ofs);
                float2 dg = *reinterpret_cast<const float2*>(g_diag + ncol);
                float i0 = acc[mf][nf][g * 2 + 0] - zz.x * dg.x;
                float i1 = acc[mf][nf][g * 2 + 1] - zz.y * dg.y;
                float2 ov, oz, ow, orr;
                adex_one(i0, vv.x, ww.x, zz.x, rr.x, ov.x, oz.x, ow.x, orr.x);
                adex_one(i1, vv.y, ww.y, zz.y, rr.y, ov.y, oz.y, ow.y, orr.y);
                *reinterpret_cast<float2*>(out + 0 * (size_t)OFS + ofs) = ov;
                *reinterpret_cast<float2*>(out + 1 * (size_t)OFS + ofs) = oz;
                *reinterpret_cast<float2*>(out + 2 * (size_t)OFS + ofs) = ow;
                *reinterpret_cast<float2*>(out + 3 * (size_t)OFS + ofs) = orr;
            }
        }
    }
}

// ---------------- launch ----------------
extern "C" void kernel_launch(void* const* d_in, const int* in_sizes, int n_in,
                              void* d_out, int out_size) {
    const float* inputs = (const float*)d_in[0];
    const float* v      = (const float*)d_in[1];
    const int*   r      = (const int*)d_in[2];
    const float* w      = (const float*)d_in[3];
    const float* z      = (const float*)d_in[4];
    const float* Win    = (const float*)d_in[5];
    const float* Wrec   = (const float*)d_in[6];
    float* out = (float*)d_out;
    (void)in_sizes; (void)n_in; (void)out_size;

    cudaFuncSetAttribute(adex_gemm_kernel,
                         cudaFuncAttributeMaxDynamicSharedMemorySize, GEMM_SMEM);

    prep_kernel<<<NWCB + NPKB + NDGB, 256>>>(inputs, z, Win, Wrec);
    adex_gemm_kernel<<<256, 128, GEMM_SMEM>>>(v, r, w, z, out);
}

// round 15
// speedup vs baseline: 1.4762x; 1.0022x over previous
#include <cuda_runtime.h>
#include <cuda_bf16.h>
#include <cstdint>
#include <cstddef>

#define BATCH 512
#define NIN   2048
#define UNITS 4096
#define KTOT  6144
#define OFS   (BATCH*UNITS)

#define BM 128
#define BN 64
#define BK 64                  // K per stage
#define STAGES 4
#define NKS (KTOT/BK)          // 96
#define A_BYTES 16384u         // 128 m-rows x 128 B
#define STAGE_BYTES 24576u     // A 16K + B 8K
#define GEMM_SMEM (STAGES*STAGE_BYTES + 1024u)   // 99328 -> 2 CTAs/SM

#define SWZA(x) ((x) ^ (((x) >> 3) & 0x70u))     // 128-B pitch swizzle

#define NWCB ((KTOT*UNITS/4)/256)  // 24576
#define NPKB (BATCH*KTOT/512)      // 6144
#define NDGB (UNITS/256)           // 16

#define C_EL      (-70.6f)
#define C_THR     (-50.4f)
#define C_DTGLC   ((float)(30.0/281.0))
#define C_INVCAP  ((float)(1.0/281.0))
#define C_DTTAUW  ((float)(1.0/144.0))
#define C_DTATAUW ((float)(4.0/144.0))
#define C_BW      (0.0805f)
#define C_VRST    (-70.6f)
#define C_CLIP    (281.0f)

__device__ __nv_bfloat16 g_Apack[(size_t)BATCH * KTOT];
__device__ __nv_bfloat16 g_Wbf[(size_t)KTOT * UNITS];
__device__ float g_diag[UNITS];

__device__ __forceinline__ uint32_t smem_u32(const void* p) {
    uint32_t a;
    asm("{ .reg .u64 t; cvta.to.shared.u64 t, %1; cvt.u32.u64 %0, t; }"
        : "=r"(a) : "l"(p));
    return a;
}
__device__ __forceinline__ void cp16(uint32_t saddr, const void* g) {
    asm volatile("cp.async.cg.shared.global [%0], [%1], 16;"
                 :: "r"(saddr), "l"(g));
}
__device__ __forceinline__ void ldmx4(uint32_t& r0, uint32_t& r1,
                                      uint32_t& r2, uint32_t& r3, uint32_t a) {
    asm volatile("ldmatrix.sync.aligned.m8n8.x4.shared.b16 {%0,%1,%2,%3}, [%4];"
                 : "=r"(r0), "=r"(r1), "=r"(r2), "=r"(r3) : "r"(a));
}
__device__ __forceinline__ void ldmx4t(uint32_t& r0, uint32_t& r1,
                                       uint32_t& r2, uint32_t& r3, uint32_t a) {
    asm volatile("ldmatrix.sync.aligned.m8n8.x4.trans.shared.b16 {%0,%1,%2,%3}, [%4];"
                 : "=r"(r0), "=r"(r1), "=r"(r2), "=r"(r3) : "r"(a));
}
__device__ __forceinline__ void mma16816(float& d0, float& d1, float& d2, float& d3,
                                         uint32_t a0, uint32_t a1, uint32_t a2, uint32_t a3,
                                         uint32_t b0, uint32_t b1) {
    asm volatile(
        "mma.sync.aligned.m16n8k16.row.col.f32.bf16.bf16.f32 "
        "{%0,%1,%2,%3}, {%4,%5,%6,%7}, {%8,%9}, {%0,%1,%2,%3};"
        : "+f"(d0), "+f"(d1), "+f"(d2), "+f"(d3)
        : "r"(a0), "r"(a1), "r"(a2), "r"(a3), "r"(b0), "r"(b1));
}

// ---------------- prep: convert W -> bf16, pack A, extract diag ----------
__global__ void __launch_bounds__(256)
prep_kernel(const float* __restrict__ inp, const float* __restrict__ z,
            const float* __restrict__ Win, const float* __restrict__ Wrec) {
    int blk = blockIdx.x;
    int tid = threadIdx.x;
    if (blk < NWCB) {
        size_t e = ((size_t)blk * 256 + tid) * 4;
        const float* src = (e < (size_t)NIN * UNITS)
                         ? (Win + e) : (Wrec + (e - (size_t)NIN * UNITS));
        float4 f = *reinterpret_cast<const float4*>(src);
        __nv_bfloat162 p0 = __floats2bfloat162_rn(f.x, f.y);
        __nv_bfloat162 p1 = __floats2bfloat162_rn(f.z, f.w);
        uint2 pk;
        pk.x = *reinterpret_cast<uint32_t*>(&p0);
        pk.y = *reinterpret_cast<uint32_t*>(&p1);
        reinterpret_cast<uint2*>(g_Wbf)[e / 4] = pk;
    } else if (blk < NWCB + NPKB) {
        int idx = (blk - NWCB) * 256 + tid;
        int b = idx / (KTOT / 2);
        int c = idx - b * (KTOT / 2);
        int k = 2 * c;
        float x0, x1;
        if (k < NIN) {
            const float* p = inp + (size_t)b * NIN + k;
            x0 = p[0]; x1 = p[1];
        } else {
            const float* p = z + (size_t)b * UNITS + (k - NIN);
            x0 = p[0]; x1 = p[1];
        }
        reinterpret_cast<__nv_bfloat162*>(g_Apack)[idx] = __floats2bfloat162_rn(x0, x1);
    } else {
        int n = (blk - NWCB - NPKB) * 256 + tid;
        g_diag[n] = __bfloat162float(__float2bfloat16(Wrec[(size_t)n * UNITS + n]));
    }
}

// ---------------- stage loader (128 threads) ----------------
__device__ __forceinline__ void load_stage(uint32_t tiles, int tid,
                                           const __nv_bfloat16* Ag,
                                           const __nv_bfloat16* Bg,
                                           int ks, int s) {
    uint32_t abase = tiles + (uint32_t)s * STAGE_BYTES;
    uint32_t bbase = abase + A_BYTES;
    const __nv_bfloat16* ag = Ag + ks * BK;
    const __nv_bfloat16* bg = Bg + (size_t)(ks * BK) * UNITS;
    #pragma unroll
    for (int i = 0; i < 8; i++) {           // A: 128 m-rows x 8 chunks(16B)
        int id = tid + i * 128;
        int row = id >> 3, cg = id & 7;
        uint32_t off = SWZA((uint32_t)(row * 128 + cg * 16));
        cp16(abase + off, ag + (size_t)row * KTOT + cg * 8);
    }
    #pragma unroll
    for (int i = 0; i < 4; i++) {           // B: 64 k-rows x 8 chunks(16B)
        int id = tid + i * 128;
        int row = id >> 3, cg = id & 7;
        uint32_t off = SWZA((uint32_t)(row * 128 + cg * 16));
        cp16(bbase + off, bg + (size_t)row * UNITS + cg * 8);
    }
}

// ---------------- AdEx elementwise ----------------
__device__ __forceinline__ void adex_one(float it, float vo, float wo, float zo,
                                         int ro, float& nv, float& nz,
                                         float& nw, float& nr) {
    float ex = expf((vo - C_THR) * 0.5f);
    ex = fminf(ex, C_CLIP);
    float nv0 = vo - C_DTGLC * (vo - C_EL) + (2.0f * C_DTGLC) * ex
              + (it - wo) * C_INVCAP;
    nv = (zo > 0.5f) ? C_VRST : nv0;
    nw = wo - wo * C_DTTAUW + C_DTATAUW * (vo - C_EL) + C_BW * zo;
    bool sp = (nv > C_THR) && (ro <= 0);
    nz = sp ? 1.0f : 0.0f;
    int nri = ro - 1 + (sp ? 2 : 0);
    nri = nri < 0 ? 0 : (nri > 2 ? 2 : nri);
    nr = (float)nri;
}

// ---------------- GEMM: 4 warps, 128x64 CTA, 2 CTAs/SM, interleaved ------
__global__ void __launch_bounds__(128, 2)
adex_gemm_kernel(const float* __restrict__ v_in, const int* __restrict__ r_in,
                 const float* __restrict__ w_in, const float* __restrict__ z_in,
                 float* __restrict__ out) {
    extern __shared__ char smem[];
    uint32_t tiles = (smem_u32(smem) + 1023u) & ~1023u;
    int tid = threadIdx.x;
    int wid = tid >> 5;
    int lane = tid & 31;

    int m0 = (blockIdx.x & 3) * BM;
    int n0 = (blockIdx.x >> 2) * BN;
    int wm = (wid & 1) * 64;     // 2 warps in M
    int wn = (wid >> 1) * 32;    // 2 warps in N

    const __nv_bfloat16* Ag = g_Apack + (size_t)m0 * KTOT;
    const __nv_bfloat16* Bg = g_Wbf + n0;

    float acc[4][4][4];
    #pragma unroll
    for (int i = 0; i < 4; i++)
        #pragma unroll
        for (int j = 0; j < 4; j++)
            #pragma unroll
            for (int q = 0; q < 4; q++) acc[i][j][q] = 0.0f;

    #pragma unroll
    for (int s = 0; s < STAGES - 1; ++s) {
        load_stage(tiles, tid, Ag, Bg, s, s);
        asm volatile("cp.async.commit_group;");
    }

    int lrow = lane & 15;
    int lcg  = (lane >> 4) * 16;

    uint32_t aoff[4];
    #pragma unroll
    for (int mf = 0; mf < 4; ++mf)
        aoff[mf] = (uint32_t)((wm + mf * 16 + lrow) * 128 + lcg);
    uint32_t boff[2];
    #pragma unroll
    for (int p = 0; p < 2; ++p)
        boff[p] = (uint32_t)(lrow * 128 + wn * 2 + p * 32 + lcg);

    for (int ks = 0; ks < NKS; ++ks) {
        int s = ks & (STAGES - 1);
        asm volatile("cp.async.wait_group %0;" :: "n"(2));
        __syncthreads();

        int kn = ks + STAGES - 1;
        if (kn < NKS) load_stage(tiles, tid, Ag, Bg, kn, kn & (STAGES - 1));
        asm volatile("cp.async.commit_group;");

        uint32_t abase = tiles + (uint32_t)s * STAGE_BYTES;
        uint32_t bbase = abase + A_BYTES;

        uint32_t af[2][4][4], bfr[2][4][2];

        // preload fragments for kk=0
        #pragma unroll
        for (int mf = 0; mf < 4; ++mf)
            ldmx4(af[0][mf][0], af[0][mf][1], af[0][mf][2], af[0][mf][3],
                  abase + SWZA(aoff[mf]));
        #pragma unroll
        for (int p = 0; p < 2; ++p) {
            uint32_t r0, r1, r2, r3;
            ldmx4t(r0, r1, r2, r3, bbase + SWZA(boff[p]));
            bfr[0][p * 2 + 0][0] = r0; bfr[0][p * 2 + 0][1] = r1;
            bfr[0][p * 2 + 1][0] = r2; bfr[0][p * 2 + 1][1] = r3;
        }

        #pragma unroll
        for (int kk = 0; kk < BK / 16; ++kk) {   // 4 k-steps
            int cur = kk & 1, nxt = cur ^ 1;
            bool pre = (kk < BK / 16 - 1);
            uint32_t kba = (uint32_t)((kk + 1) * 32);    // A: +16 bf16 in k
            uint32_t kbb = (uint32_t)((kk + 1) * 2048);  // B: +16 k-rows

            // ---- interleaved: 2-3 MMA between each LDSM (order preserved
            //      by asm volatile) so tensor + crossbar stay co-fed ----
            #define MMA_AT(MF,NF) \
                mma16816(acc[MF][NF][0], acc[MF][NF][1], \
                         acc[MF][NF][2], acc[MF][NF][3], \
                         af[cur][MF][0], af[cur][MF][1], \
                         af[cur][MF][2], af[cur][MF][3], \
                         bfr[cur][NF][0], bfr[cur][NF][1])

            MMA_AT(0, 0); MMA_AT(0, 1);
            if (pre) ldmx4(af[nxt][0][0], af[nxt][0][1], af[nxt][0][2],
                           af[nxt][0][3], abase + SWZA(aoff[0] + kba));
            MMA_AT(0, 2); MMA_AT(0, 3);
            if (pre) ldmx4(af[nxt][1][0], af[nxt][1][1], af[nxt][1][2],
                           af[nxt][1][3], abase + SWZA(aoff[1] + kba));
            MMA_AT(1, 0); MMA_AT(1, 1);
            if (pre) ldmx4(af[nxt][2][0], af[nxt][2][1], af[nxt][2][2],
                           af[nxt][2][3], abase + SWZA(aoff[2] + kba));
            MMA_AT(1, 2); MMA_AT(1, 3);
            if (pre) ldmx4(af[nxt][3][0], af[nxt][3][1], af[nxt][3][2],
                           af[nxt][3][3], abase + SWZA(aoff[3] + kba));
            MMA_AT(2, 0); MMA_AT(2, 1);
            if (pre) {
                uint32_t r0, r1, r2, r3;
                ldmx4t(r0, r1, r2, r3, bbase + SWZA(boff[0] + kbb));
                bfr[nxt][0][0] = r0; bfr[nxt][0][1] = r1;
                bfr[nxt][1][0] = r2; bfr[nxt][1][1] = r3;
            }
            MMA_AT(2, 2); MMA_AT(2, 3);
            if (pre) {
                uint32_t r0, r1, r2, r3;
                ldmx4t(r0, r1, r2, r3, bbase + SWZA(boff[1] + kbb));
                bfr[nxt][2][0] = r0; bfr[nxt][2][1] = r1;
                bfr[nxt][3][0] = r2; bfr[nxt][3][1] = r3;
            }
            MMA_AT(3, 0); MMA_AT(3, 1); MMA_AT(3, 2); MMA_AT(3, 3);
            #undef MMA_AT
        }
    }

    // ------------- epilogue -------------
    int gid = lane >> 2;
    int qn  = (lane & 3) * 2;

    #pragma unroll
    for (int mf = 0; mf < 4; ++mf) {
        #pragma unroll
        for (int g = 0; g < 2; ++g) {
            int b = m0 + wm + mf * 16 + g * 8 + gid;
            size_t rowbase = (size_t)b * UNITS + n0 + wn;
            #pragma unroll
            for (int nf = 0; nf < 4; ++nf) {
                size_t ofs = rowbase + nf * 8 + qn;
                int ncol = n0 + wn + nf * 8 + qn;
                float2 vv = *reinterpret_cast<const float2*>(v_in + ofs);
                float2 ww = *reinterpret_cast<const float2*>(w_in + ofs);
                float2 zz = *reinterpret_cast<const float2*>(z_in + ofs);
                int2   rr = *reinterpret_cast<const int2*>(r_in + ofs);
                float2 dg = *reinterpret_cast<const float2*>(g_diag + ncol);
                float i0 = acc[mf][nf][g * 2 + 0] - zz.x * dg.x;
                float i1 = acc[mf][nf][g * 2 + 1] - zz.y * dg.y;
                float2 ov, oz, ow, orr;
                adex_one(i0, vv.x, ww.x, zz.x, rr.x, ov.x, oz.x, ow.x, orr.x);
                adex_one(i1, vv.y, ww.y, zz.y, rr.y, ov.y, oz.y, ow.y, orr.y);
                *reinterpret_cast<float2*>(out + 0 * (size_t)OFS + ofs) = ov;
                *reinterpret_cast<float2*>(out + 1 * (size_t)OFS + ofs) = oz;
                *reinterpret_cast<float2*>(out + 2 * (size_t)OFS + ofs) = ow;
                *reinterpret_cast<float2*>(out + 3 * (size_t)OFS + ofs) = orr;
            }
        }
    }
}

// ---------------- launch ----------------
extern "C" void kernel_launch(void* const* d_in, const int* in_sizes, int n_in,
                              void* d_out, int out_size) {
    const float* inputs = (const float*)d_in[0];
    const float* v      = (const float*)d_in[1];
    const int*   r      = (const int*)d_in[2];
    const float* w      = (const float*)d_in[3];
    const float* z      = (const float*)d_in[4];
    const float* Win    = (const float*)d_in[5];
    const float* Wrec   = (const float*)d_in[6];
    float* out = (float*)d_out;
    (void)in_sizes; (void)n_in; (void)out_size;

    cudaFuncSetAttribute(adex_gemm_kernel,
                         cudaFuncAttributeMaxDynamicSharedMemorySize, GEMM_SMEM);

    prep_kernel<<<NWCB + NPKB + NDGB, 256>>>(inputs, z, Win, Wrec);
    adex_gemm_kernel<<<256, 128, GEMM_SMEM>>>(v, r, w, z, out);
}

// round 16
// speedup vs baseline: 1.5364x; 1.0408x over previous
#include <cuda_runtime.h>
#include <cuda_bf16.h>
#include <cstdint>
#include <cstddef>

#define BATCH 512
#define NIN   2048
#define UNITS 4096
#define KTOT  6144
#define OFS   (BATCH*UNITS)

#define BM 128
#define BN 64
#define BK 64                  // K per stage
#define STAGES 4
#define NKS (KTOT/BK)          // 96
#define A_BYTES 16384u         // 128 m-rows x 128 B
#define STAGE_BYTES 24576u     // A 16K + B 8K
#define GEMM_SMEM (STAGES*STAGE_BYTES + 1024u)   // 99328 -> 2 CTAs/SM

#define SWZA(x) ((x) ^ (((x) >> 3) & 0x70u))     // 128-B pitch swizzle

// prep block ranges (512-thread blocks)
#define NW2B ((KTOT*UNITS/8)/512)   // 6144 : W convert, 8 elem/thread
#define NPK2 ((BATCH*KTOT/4)/512)   // 1536 : A pack, 4 elem/thread
#define NDG2 (UNITS/512)            // 8    : diag

#define C_EL      (-70.6f)
#define C_THR     (-50.4f)
#define C_DTGLC   ((float)(30.0/281.0))
#define C_INVCAP  ((float)(1.0/281.0))
#define C_DTTAUW  ((float)(1.0/144.0))
#define C_DTATAUW ((float)(4.0/144.0))
#define C_BW      (0.0805f)
#define C_VRST    (-70.6f)
#define C_CLIP    (281.0f)

__device__ __nv_bfloat16 g_Apack[(size_t)BATCH * KTOT];
__device__ __nv_bfloat16 g_Wbf[(size_t)KTOT * UNITS];
__device__ float g_diag[UNITS];

__device__ __forceinline__ uint32_t smem_u32(const void* p) {
    uint32_t a;
    asm("{ .reg .u64 t; cvta.to.shared.u64 t, %1; cvt.u32.u64 %0, t; }"
        : "=r"(a) : "l"(p));
    return a;
}
__device__ __forceinline__ void cp16(uint32_t saddr, const void* g) {
    asm volatile("cp.async.cg.shared.global [%0], [%1], 16;"
                 :: "r"(saddr), "l"(g));
}
__device__ __forceinline__ void ldmx4(uint32_t& r0, uint32_t& r1,
                                      uint32_t& r2, uint32_t& r3, uint32_t a) {
    asm volatile("ldmatrix.sync.aligned.m8n8.x4.shared.b16 {%0,%1,%2,%3}, [%4];"
                 : "=r"(r0), "=r"(r1), "=r"(r2), "=r"(r3) : "r"(a));
}
__device__ __forceinline__ void ldmx4t(uint32_t& r0, uint32_t& r1,
                                       uint32_t& r2, uint32_t& r3, uint32_t a) {
    asm volatile("ldmatrix.sync.aligned.m8n8.x4.trans.shared.b16 {%0,%1,%2,%3}, [%4];"
                 : "=r"(r0), "=r"(r1), "=r"(r2), "=r"(r3) : "r"(a));
}
__device__ __forceinline__ void mma16816(float& d0, float& d1, float& d2, float& d3,
                                         uint32_t a0, uint32_t a1, uint32_t a2, uint32_t a3,
                                         uint32_t b0, uint32_t b1) {
    asm volatile(
        "mma.sync.aligned.m16n8k16.row.col.f32.bf16.bf16.f32 "
        "{%0,%1,%2,%3}, {%4,%5,%6,%7}, {%8,%9}, {%0,%1,%2,%3};"
        : "+f"(d0), "+f"(d1), "+f"(d2), "+f"(d3)
        : "r"(a0), "r"(a1), "r"(a2), "r"(a3), "r"(b0), "r"(b1));
}

__device__ __forceinline__ uint2 cvt4(float4 f) {
    __nv_bfloat162 p0 = __floats2bfloat162_rn(f.x, f.y);
    __nv_bfloat162 p1 = __floats2bfloat162_rn(f.z, f.w);
    uint2 pk;
    pk.x = *reinterpret_cast<uint32_t*>(&p0);
    pk.y = *reinterpret_cast<uint32_t*>(&p1);
    return pk;
}

// ---------------- prep: convert W -> bf16, pack A, extract diag ----------
// 512-thread blocks; W: 8 elems/thread (2x float4, MLP=2); pack: 4 elems/thread
__global__ void __launch_bounds__(512)
prep_kernel(const float* __restrict__ inp, const float* __restrict__ z,
            const float* __restrict__ Win, const float* __restrict__ Wrec) {
    int blk = blockIdx.x;
    int tid = threadIdx.x;

    if (blk < NW2B) {
        size_t e = ((size_t)blk * 512 + tid) * 8;
        const float* src = (e < (size_t)NIN * UNITS)
                         ? (Win + e) : (Wrec + (e - (size_t)NIN * UNITS));
        float4 f0 = *reinterpret_cast<const float4*>(src);
        float4 f1 = *reinterpret_cast<const float4*>(src + 4);
        uint2 q0 = cvt4(f0);
        uint2 q1 = cvt4(f1);
        uint4 o;
        o.x = q0.x; o.y = q0.y; o.z = q1.x; o.w = q1.y;
        *reinterpret_cast<uint4*>(g_Wbf + e) = o;
    } else if (blk < NW2B + NPK2) {
        int idx = (blk - NW2B) * 512 + tid;     // float4 groups
        int b = idx / (KTOT / 4);
        int c = idx - b * (KTOT / 4);
        int k = 4 * c;
        float4 f;
        if (k < NIN) {
            f = *reinterpret_cast<const float4*>(inp + (size_t)b * NIN + k);
        } else {
            f = *reinterpret_cast<const float4*>(z + (size_t)b * UNITS + (k - NIN));
        }
        reinterpret_cast<uint2*>(g_Apack)[idx] = cvt4(f);
    } else {
        int n = (blk - NW2B - NPK2) * 512 + tid;
        g_diag[n] = __bfloat162float(__float2bfloat16(Wrec[(size_t)n * UNITS + n]));
    }
}

// ---------------- stage loader (128 threads) ----------------
__device__ __forceinline__ void load_stage(uint32_t tiles, int tid,
                                           const __nv_bfloat16* Ag,
                                           const __nv_bfloat16* Bg,
                                           int ks, int s) {
    uint32_t abase = tiles + (uint32_t)s * STAGE_BYTES;
    uint32_t bbase = abase + A_BYTES;
    const __nv_bfloat16* ag = Ag + ks * BK;
    const __nv_bfloat16* bg = Bg + (size_t)(ks * BK) * UNITS;
    #pragma unroll
    for (int i = 0; i < 8; i++) {           // A: 128 m-rows x 8 chunks(16B)
        int id = tid + i * 128;
        int row = id >> 3, cg = id & 7;
        uint32_t off = SWZA((uint32_t)(row * 128 + cg * 16));
        cp16(abase + off, ag + (size_t)row * KTOT + cg * 8);
    }
    #pragma unroll
    for (int i = 0; i < 4; i++) {           // B: 64 k-rows x 8 chunks(16B)
        int id = tid + i * 128;
        int row = id >> 3, cg = id & 7;
        uint32_t off = SWZA((uint32_t)(row * 128 + cg * 16));
        cp16(bbase + off, bg + (size_t)row * UNITS + cg * 8);
    }
}

// ---------------- AdEx elementwise ----------------
__device__ __forceinline__ void adex_one(float it, float vo, float wo, float zo,
                                         int ro, float& nv, float& nz,
                                         float& nw, float& nr) {
    float ex = expf((vo - C_THR) * 0.5f);
    ex = fminf(ex, C_CLIP);
    float nv0 = vo - C_DTGLC * (vo - C_EL) + (2.0f * C_DTGLC) * ex
              + (it - wo) * C_INVCAP;
    nv = (zo > 0.5f) ? C_VRST : nv0;
    nw = wo - wo * C_DTTAUW + C_DTATAUW * (vo - C_EL) + C_BW * zo;
    bool sp = (nv > C_THR) && (ro <= 0);
    nz = sp ? 1.0f : 0.0f;
    int nri = ro - 1 + (sp ? 2 : 0);
    nri = nri < 0 ? 0 : (nri > 2 ? 2 : nri);
    nr = (float)nri;
}

// ---------------- GEMM: 4 warps, 128x64 CTA, 2 CTAs/SM, interleaved ------
__global__ void __launch_bounds__(128, 2)
adex_gemm_kernel(const float* __restrict__ v_in, const int* __restrict__ r_in,
                 const float* __restrict__ w_in, const float* __restrict__ z_in,
                 float* __restrict__ out) {
    extern __shared__ char smem[];
    uint32_t tiles = (smem_u32(smem) + 1023u) & ~1023u;
    int tid = threadIdx.x;
    int wid = tid >> 5;
    int lane = tid & 31;

    int m0 = (blockIdx.x & 3) * BM;
    int n0 = (blockIdx.x >> 2) * BN;
    int wm = (wid & 1) * 64;     // 2 warps in M
    int wn = (wid >> 1) * 32;    // 2 warps in N

    const __nv_bfloat16* Ag = g_Apack + (size_t)m0 * KTOT;
    const __nv_bfloat16* Bg = g_Wbf + n0;

    float acc[4][4][4];
    #pragma unroll
    for (int i = 0; i < 4; i++)
        #pragma unroll
        for (int j = 0; j < 4; j++)
            #pragma unroll
            for (int q = 0; q < 4; q++) acc[i][j][q] = 0.0f;

    #pragma unroll
    for (int s = 0; s < STAGES - 1; ++s) {
        load_stage(tiles, tid, Ag, Bg, s, s);
        asm volatile("cp.async.commit_group;");
    }

    int lrow = lane & 15;
    int lcg  = (lane >> 4) * 16;

    uint32_t aoff[4];
    #pragma unroll
    for (int mf = 0; mf < 4; ++mf)
        aoff[mf] = (uint32_t)((wm + mf * 16 + lrow) * 128 + lcg);
    uint32_t boff[2];
    #pragma unroll
    for (int p = 0; p < 2; ++p)
        boff[p] = (uint32_t)(lrow * 128 + wn * 2 + p * 32 + lcg);

    for (int ks = 0; ks < NKS; ++ks) {
        int s = ks & (STAGES - 1);
        asm volatile("cp.async.wait_group %0;" :: "n"(2));
        __syncthreads();

        int kn = ks + STAGES - 1;
        if (kn < NKS) load_stage(tiles, tid, Ag, Bg, kn, kn & (STAGES - 1));
        asm volatile("cp.async.commit_group;");

        uint32_t abase = tiles + (uint32_t)s * STAGE_BYTES;
        uint32_t bbase = abase + A_BYTES;

        uint32_t af[2][4][4], bfr[2][4][2];

        // preload fragments for kk=0
        #pragma unroll
        for (int mf = 0; mf < 4; ++mf)
            ldmx4(af[0][mf][0], af[0][mf][1], af[0][mf][2], af[0][mf][3],
                  abase + SWZA(aoff[mf]));
        #pragma unroll
        for (int p = 0; p < 2; ++p) {
            uint32_t r0, r1, r2, r3;
            ldmx4t(r0, r1, r2, r3, bbase + SWZA(boff[p]));
            bfr[0][p * 2 + 0][0] = r0; bfr[0][p * 2 + 0][1] = r1;
            bfr[0][p * 2 + 1][0] = r2; bfr[0][p * 2 + 1][1] = r3;
        }

        #pragma unroll
        for (int kk = 0; kk < BK / 16; ++kk) {   // 4 k-steps
            int cur = kk & 1, nxt = cur ^ 1;
            bool pre = (kk < BK / 16 - 1);
            uint32_t kba = (uint32_t)((kk + 1) * 32);    // A: +16 bf16 in k
            uint32_t kbb = (uint32_t)((kk + 1) * 2048);  // B: +16 k-rows

            #define MMA_AT(MF,NF) \
                mma16816(acc[MF][NF][0], acc[MF][NF][1], \
                         acc[MF][NF][2], acc[MF][NF][3], \
                         af[cur][MF][0], af[cur][MF][1], \
                         af[cur][MF][2], af[cur][MF][3], \
                         bfr[cur][NF][0], bfr[cur][NF][1])

            MMA_AT(0, 0); MMA_AT(0, 1);
            if (pre) ldmx4(af[nxt][0][0], af[nxt][0][1], af[nxt][0][2],
                           af[nxt][0][3], abase + SWZA(aoff[0] + kba));
            MMA_AT(0, 2); MMA_AT(0, 3);
            if (pre) ldmx4(af[nxt][1][0], af[nxt][1][1], af[nxt][1][2],
                           af[nxt][1][3], abase + SWZA(aoff[1] + kba));
            MMA_AT(1, 0); MMA_AT(1, 1);
            if (pre) ldmx4(af[nxt][2][0], af[nxt][2][1], af[nxt][2][2],
                           af[nxt][2][3], abase + SWZA(aoff[2] + kba));
            MMA_AT(1, 2); MMA_AT(1, 3);
            if (pre) ldmx4(af[nxt][3][0], af[nxt][3][1], af[nxt][3][2],
                           af[nxt][3][3], abase + SWZA(aoff[3] + kba));
            MMA_AT(2, 0); MMA_AT(2, 1);
            if (pre) {
                uint32_t r0, r1, r2, r3;
                ldmx4t(r0, r1, r2, r3, bbase + SWZA(boff[0] + kbb));
                bfr[nxt][0][0] = r0; bfr[nxt][0][1] = r1;
                bfr[nxt][1][0] = r2; bfr[nxt][1][1] = r3;
            }
            MMA_AT(2, 2); MMA_AT(2, 3);
            if (pre) {
                uint32_t r0, r1, r2, r3;
                ldmx4t(r0, r1, r2, r3, bbase + SWZA(boff[1] + kbb));
                bfr[nxt][2][0] = r0; bfr[nxt][2][1] = r1;
                bfr[nxt][3][0] = r2; bfr[nxt][3][1] = r3;
            }
            MMA_AT(3, 0); MMA_AT(3, 1); MMA_AT(3, 2); MMA_AT(3, 3);
            #undef MMA_AT
        }
    }

    // ------------- epilogue -------------
    int gid = lane >> 2;
    int qn  = (lane & 3) * 2;

    #pragma unroll
    for (int mf = 0; mf < 4; ++mf) {
        #pragma unroll
        for (int g = 0; g < 2; ++g) {
            int b = m0 + wm + mf * 16 + g * 8 + gid;
            size_t rowbase = (size_t)b * UNITS + n0 + wn;
            #pragma unroll
            for (int nf = 0; nf < 4; ++nf) {
                size_t ofs = rowbase + nf * 8 + qn;
                int ncol = n0 + wn + nf * 8 + qn;
                float2 vv = *reinterpret_cast<const float2*>(v_in + ofs);
                float2 ww = *reinterpret_cast<const float2*>(w_in + ofs);
                float2 zz = *reinterpret_cast<const float2*>(z_in + ofs);
                int2   rr = *reinterpret_cast<const int2*>(r_in + ofs);
                float2 dg = *reinterpret_cast<const float2*>(g_diag + ncol);
                float i0 = acc[mf][nf][g * 2 + 0] - zz.x * dg.x;
                float i1 = acc[mf][nf][g * 2 + 1] - zz.y * dg.y;
                float2 ov, oz, ow, orr;
                adex_one(i0, vv.x, ww.x, zz.x, rr.x, ov.x, oz.x, ow.x, orr.x);
                adex_one(i1, vv.y, ww.y, zz.y, rr.y, ov.y, oz.y, ow.y, orr.y);
                *reinterpret_cast<float2*>(out + 0 * (size_t)OFS + ofs) = ov;
                *reinterpret_cast<float2*>(out + 1 * (size_t)OFS + ofs) = oz;
                *reinterpret_cast<float2*>(out + 2 * (size_t)OFS + ofs) = ow;
                *reinterpret_cast<float2*>(out + 3 * (size_t)OFS + ofs) = orr;
            }
        }
    }
}

// ---------------- launch ----------------
extern "C" void kernel_launch(void* const* d_in, const int* in_sizes, int n_in,
                              void* d_out, int out_size) {
    const float* inputs = (const float*)d_in[0];
    const float* v      = (const float*)d_in[1];
    const int*   r      = (const int*)d_in[2];
    const float* w      = (const float*)d_in[3];
    const float* z      = (const float*)d_in[4];
    const float* Win    = (const float*)d_in[5];
    const float* Wrec   = (const float*)d_in[6];
    float* out = (float*)d_out;
    (void)in_sizes; (void)n_in; (void)out_size;

    cudaFuncSetAttribute(adex_gemm_kernel,
                         cudaFuncAttributeMaxDynamicSharedMemorySize, GEMM_SMEM);

    prep_kernel<<<NW2B + NPK2 + NDG2, 512>>>(inputs, z, Win, Wrec);
    adex_gemm_kernel<<<256, 128, GEMM_SMEM>>>(v, r, w, z, out);
}